// round 1
// baseline (speedup 1.0000x reference)
#include <cuda_runtime.h>

// ---------------------------------------------------------------------------
// DownSample_7945689498135
// Inputs (metadata order):
//  0 sparse_fea [64,256,64]  1 dense_fea [64,128,4096]  2 stk_coor [64,64,32]
//  3 conv_w [256,128,1,3]    4 conv_b [256] (unused: cancels in BN)
//  5 bn_gamma [256]          6 bn_beta [256]
// Output (float32, concat): sparse_out [64,256,32] | dense_out [64,256,1024] |
//                           stk_coor_sampled [64,32,32]
// ---------------------------------------------------------------------------

#define BSZ    64
#define SPEMB  256
#define DIN    128
#define DOUT   256
#define NSTK   64
#define NHALF  32
#define NPNT   64
#define QOUT   32

#define SP_OFF 0
#define DN_OFF (BSZ*SPEMB*NHALF)            // 524288
#define CO_OFF (DN_OFF + BSZ*DOUT*NHALF*QOUT) // 17301504

// scratch (device globals: allocation-free per harness rules)
__device__ float  g_y[BSZ*DOUT*NHALF*QOUT];   // 64 MB conv output
__device__ float4 g_wA[DIN*128];              // (w0_lo,w0_hi,w1_lo,w1_hi) per (i, t)
__device__ float2 g_wB[DIN*128];              // (w2_lo,w2_hi)
__device__ float  g_sum[DOUT], g_sumsq[DOUT];
__device__ float  g_scale[DOUT], g_shift[DOUT];
__device__ int    g_fps[BSZ*NHALF];

#define FMA2(d, a, b, c) \
    asm("fma.rn.f32x2 %0, %1, %2, %3;" : "=l"(d) : "l"(a), "l"(b), "l"(c))

// ---------------------------------------------------------------------------
// init: transpose weights into channel-pair packed layout; zero BN accumulators
// ---------------------------------------------------------------------------
__global__ void init_kernel(const float* __restrict__ w) {
    int idx = blockIdx.x * 256 + threadIdx.x;      // 0..16383
    int i = idx >> 7, t = idx & 127;
    const float* wlo = w + t * 384 + i * 3;
    const float* whi = w + (t + 128) * 384 + i * 3;
    g_wA[i * 128 + t] = make_float4(wlo[0], whi[0], wlo[1], whi[1]);
    g_wB[i * 128 + t] = make_float2(wlo[2], whi[2]);
    if (idx < DOUT) { g_sum[idx] = 0.f; g_sumsq[idx] = 0.f; }
}

// ---------------------------------------------------------------------------
// FPS: one block per batch, 64 threads (one per point). Matches jnp semantics:
// dists=1e10, far=0; iter i: record far, min-update dists, argmax (first-max).
// Also writes stk_coor_sampled.
// ---------------------------------------------------------------------------
__global__ void fps_kernel(const float* __restrict__ coor, float* __restrict__ out3) {
    __shared__ float sh[NSTK * 33];   // padded stride 33: conflict-free row reads
    __shared__ float sd[NSTK];
    __shared__ int   si[NSTK];
    __shared__ int   sel[NHALF];
    int b = blockIdx.x, t = threadIdx.x;
    const float* src = coor + b * NSTK * 32;
#pragma unroll
    for (int r = 0; r < 32; r++) {
        int l = r * 64 + t;                       // n*32 + c
        sh[(l >> 5) * 33 + (l & 31)] = src[l];
    }
    __syncthreads();

    float mind = 1e10f;
    int far = 0;
    const float* mine = sh + t * 33;
    for (int i = 0; i < NHALF; i++) {
        if (t == 0) { sel[i] = far; g_fps[b * NHALF + i] = far; }
        const float* cent = sh + far * 33;
        float d = 0.f;
#pragma unroll
        for (int c = 0; c < 32; c++) { float df = mine[c] - cent[c]; d = fmaf(df, df, d); }
        mind = fminf(mind, d);
        sd[t] = mind; si[t] = t;
        __syncthreads();
        for (int off = 32; off; off >>= 1) {
            if (t < off) {
                float d2 = sd[t + off]; int i2 = si[t + off];
                if (d2 > sd[t] || (d2 == sd[t] && i2 < si[t])) { sd[t] = d2; si[t] = i2; }
            }
            __syncthreads();
        }
        far = si[0];
        __syncthreads();
    }
    // gather sampled coordinates: [32, 32] per batch
#pragma unroll
    for (int r = 0; r < 16; r++) {
        int l = r * 64 + t;                       // ii*32 + c
        out3[b * 1024 + l] = sh[sel[l >> 5] * 33 + (l & 31)];
    }
}

// ---------------------------------------------------------------------------
// sparse gather: out[b,c,j] = sparse[b,c,idx[b,j]]
// ---------------------------------------------------------------------------
__global__ void gather_sparse(const float* __restrict__ sp, float* __restrict__ outp) {
    int idx = blockIdx.x * 256 + threadIdx.x;     // < 524288
    int b = idx >> 13;
    int r = idx & 8191;
    int c = r >> 5, jj = r & 31;
    outp[idx] = sp[b * (SPEMB * NSTK) + c * NSTK + g_fps[b * NHALF + jj]];
}

// ---------------------------------------------------------------------------
// conv: one block per (b, stroke j). 128 threads; thread t computes channels
// t and t+128 packed as f32x2. x rows are stored DUPLICATED in SMEM as
// (x, x) float2 pairs so the inner loop is 1 LDS.128 + 3 FFMA2 per q.
// Weights pre-packed (g_wA/g_wB) -> 1 LDG.128 + 1 LDG.64 per i, coalesced.
// Epilogue writes y and accumulates per-channel sum / sumsq via atomics.
// ---------------------------------------------------------------------------
__global__ void __launch_bounds__(128) conv_kernel(const float* __restrict__ dense) {
    __shared__ __align__(16) float4 xs4[64 * 34];  // 64 rows x 68 dup-pairs (34 f4)
    int t = threadIdx.x;
    int b = blockIdx.x >> 5, j = blockIdx.x & 31;
    int s = g_fps[b * NHALF + j];
    const float4* src = reinterpret_cast<const float4*>(dense + b * (DIN * 4096) + s * 64);

    unsigned long long acc[QOUT];
#pragma unroll
    for (int q = 0; q < QOUT; q++) acc[q] = 0ull;

    const ulonglong2* wa = reinterpret_cast<const ulonglong2*>(g_wA);
    const unsigned long long* wb = reinterpret_cast<const unsigned long long*>(g_wB);

    for (int half = 0; half < 2; half++) {
        // stage 64 input rows (64 floats each), duplicated into float2 pairs
#pragma unroll
        for (int rr = 0; rr < 8; rr++) {
            int lidx = rr * 128 + t;              // 0..1023
            int i2 = lidx >> 4, p4 = lidx & 15;
            float4 v = src[(half * 64 + i2) * 1024 + p4];
            float2* row = reinterpret_cast<float2*>(xs4 + i2 * 34);
            row[p4 * 4 + 1] = make_float2(v.x, v.x);
            row[p4 * 4 + 2] = make_float2(v.y, v.y);
            row[p4 * 4 + 3] = make_float2(v.z, v.z);
            row[p4 * 4 + 4] = make_float2(v.w, v.w);
        }
        if (t < 64) {  // zero pads xp[0], xp[65]
            float2* row = reinterpret_cast<float2*>(xs4 + t * 34);
            row[0]  = make_float2(0.f, 0.f);
            row[65] = make_float2(0.f, 0.f);
        }
        __syncthreads();

#pragma unroll 1
        for (int i2 = 0; i2 < 64; i2++) {
            int i = half * 64 + i2;
            ulonglong2 w01 = wa[i * 128 + t];     // (w0 pair, w1 pair)
            unsigned long long w2 = wb[i * 128 + t];
            const ulonglong2* rowv = reinterpret_cast<const ulonglong2*>(xs4 + i2 * 34);
            ulonglong2 cur = rowv[0];             // xp[0], xp[1] (dup pairs)
#pragma unroll
            for (int q = 0; q < QOUT; q++) {
                ulonglong2 nxt = rowv[q + 1];     // xp[2q+2], xp[2q+3]
                FMA2(acc[q], w01.x, cur.x, acc[q]);
                FMA2(acc[q], w01.y, cur.y, acc[q]);
                FMA2(acc[q], w2,    nxt.x, acc[q]);
                cur = nxt;
            }
        }
        __syncthreads();
    }

    // epilogue: unpack, store y, per-channel stats
    float slo = 0.f, s2lo = 0.f, shi = 0.f, s2hi = 0.f;
    float* ylo = g_y + ((b * DOUT + t) * NHALF + j) * QOUT;
    float* yhi = g_y + ((b * DOUT + t + 128) * NHALF + j) * QOUT;
#pragma unroll
    for (int q = 0; q < QOUT; q += 4) {
        float4 vl, vh;
        asm("mov.b64 {%0,%1}, %2;" : "=f"(vl.x), "=f"(vh.x) : "l"(acc[q]));
        asm("mov.b64 {%0,%1}, %2;" : "=f"(vl.y), "=f"(vh.y) : "l"(acc[q + 1]));
        asm("mov.b64 {%0,%1}, %2;" : "=f"(vl.z), "=f"(vh.z) : "l"(acc[q + 2]));
        asm("mov.b64 {%0,%1}, %2;" : "=f"(vl.w), "=f"(vh.w) : "l"(acc[q + 3]));
        slo  += vl.x + vl.y + vl.z + vl.w;
        s2lo += vl.x * vl.x + vl.y * vl.y + vl.z * vl.z + vl.w * vl.w;
        shi  += vh.x + vh.y + vh.z + vh.w;
        s2hi += vh.x * vh.x + vh.y * vh.y + vh.z * vh.z + vh.w * vh.w;
        *reinterpret_cast<float4*>(ylo + q) = vl;
        *reinterpret_cast<float4*>(yhi + q) = vh;
    }
    atomicAdd(&g_sum[t], slo);         atomicAdd(&g_sumsq[t], s2lo);
    atomicAdd(&g_sum[t + 128], shi);   atomicAdd(&g_sumsq[t + 128], s2hi);
}

// ---------------------------------------------------------------------------
// BN finalize: per-channel scale/shift from batch statistics (biased var)
// ---------------------------------------------------------------------------
__global__ void bn_finalize(const float* __restrict__ gamma, const float* __restrict__ beta) {
    int t = threadIdx.x;
    const float inv_n = 1.f / 65536.f;
    float m = g_sum[t] * inv_n;
    float v = g_sumsq[t] * inv_n - m * m;
    float inv = rsqrtf(v + 1e-5f);
    float g = gamma[t] * inv;
    g_scale[t] = g;
    g_shift[t] = beta[t] - m * g;
}

// ---------------------------------------------------------------------------
// BN apply + tanh-GELU (jax.nn.gelu default approximate=True), vectorized
// ---------------------------------------------------------------------------
__device__ __forceinline__ float gelu_t(float x) {
    float x3 = x * x * x;
    float u = 0.7978845608028654f * fmaf(0.044715f, x3, x);
    return 0.5f * x * (1.f + tanhf(u));
}

__global__ void bn_act_kernel(float* __restrict__ outp) {
    int idx4 = blockIdx.x * 256 + threadIdx.x;    // < 4194304
    const float4* gy4 = reinterpret_cast<const float4*>(g_y);
    float4 v = gy4[idx4];
    int o = (idx4 >> 8) & 255;
    float sc = g_scale[o], sh = g_shift[o];
    v.x = gelu_t(fmaf(v.x, sc, sh));
    v.y = gelu_t(fmaf(v.y, sc, sh));
    v.z = gelu_t(fmaf(v.z, sc, sh));
    v.w = gelu_t(fmaf(v.w, sc, sh));
    reinterpret_cast<float4*>(outp)[idx4] = v;
}

// ---------------------------------------------------------------------------
extern "C" void kernel_launch(void* const* d_in, const int* in_sizes, int n_in,
                              void* d_out, int out_size) {
    const float* sparse = (const float*)d_in[0];
    const float* dense  = (const float*)d_in[1];
    const float* coor   = (const float*)d_in[2];
    const float* convw  = (const float*)d_in[3];
    // d_in[4] = conv_b: mathematically cancels under BN mean subtraction
    const float* gamma  = (const float*)d_in[5];
    const float* beta   = (const float*)d_in[6];
    float* out = (float*)d_out;

    init_kernel<<<64, 256>>>(convw);
    fps_kernel<<<BSZ, 64>>>(coor, out + CO_OFF);
    gather_sparse<<<2048, 256>>>(sparse, out + SP_OFF);
    conv_kernel<<<BSZ * NHALF, 128>>>(dense);
    bn_finalize<<<1, DOUT>>>(gamma, beta);
    bn_act_kernel<<<16384, 256>>>(out + DN_OFF);
}

// round 7
// speedup vs baseline: 1.5983x; 1.5983x over previous
#include <cuda_runtime.h>
#include <cuda_bf16.h>
#include <cstdint>

// ---------------------------------------------------------------------------
// DownSample_7945689498135 — bf16-split HMMA (mma.sync) GEMM version
// (tcgen05 unavailable: harness compiles via compute_103, no 'a' features)
// Inputs: 0 sparse_fea[64,256,64] 1 dense_fea[64,128,4096] 2 stk_coor[64,64,32]
//         3 conv_w[256,128,1,3] 4 conv_b (cancels in BN) 5 bn_gamma 6 bn_beta
// Output fp32 concat: sparse_out[64,256,32] | dense_out[64,256,1024] | coor[64,32,32]
// ---------------------------------------------------------------------------

#define BSZ    64
#define SPEMB  256
#define DIN    128
#define DOUT   256
#define NSTK   64
#define NHALF  32
#define QOUT   32
#define KTOT   384
#define NPOS   65536
#define NCHUNK 18          // 3 passes x 6 k64-chunks

#define SP_OFF 0
#define DN_OFF (BSZ*SPEMB*NHALF)                 // 524288
#define CO_OFF (DN_OFF + BSZ*DOUT*NHALF*QOUT)    // 17301504

__device__ __nv_bfloat16 g_Xh[NPOS*KTOT];
__device__ __nv_bfloat16 g_Xl[NPOS*KTOT];
__device__ __nv_bfloat16 g_Wh[DOUT*KTOT];
__device__ __nv_bfloat16 g_Wl[DOUT*KTOT];
__device__ float g_y[BSZ*DOUT*NHALF*QOUT];
__device__ float g_sum[DOUT], g_sumsq[DOUT], g_scale[DOUT], g_shift[DOUT];
__device__ int   g_fps[BSZ*NHALF];

#define SWZ(x) ((x) ^ (((x) >> 3) & 0x70))
#define STAGE_BYTES 32768          // A 16K + B 16K
#define DYN_SMEM    (3*STAGE_BYTES)

__device__ __forceinline__ uint32_t smem_u32(const void* p) {
    uint32_t a;
    asm("{ .reg .u64 t; cvta.to.shared.u64 t, %1; cvt.u32.u64 %0, t; }" : "=r"(a) : "l"(p));
    return a;
}
__device__ __forceinline__ void cp16(uint32_t dst, const void* src) {
    asm volatile("cp.async.cg.shared.global [%0], [%1], 16;" :: "r"(dst), "l"(src));
}
#define CP_COMMIT() asm volatile("cp.async.commit_group;" ::: "memory")

__device__ __forceinline__ void ldm4(uint32_t addr, uint32_t& r0, uint32_t& r1,
                                     uint32_t& r2, uint32_t& r3) {
    asm volatile("ldmatrix.sync.aligned.m8n8.x4.shared.b16 {%0,%1,%2,%3}, [%4];"
                 : "=r"(r0), "=r"(r1), "=r"(r2), "=r"(r3) : "r"(addr));
}
__device__ __forceinline__ void mma16816(float* c, const uint32_t* a, uint32_t b0, uint32_t b1) {
    asm volatile("mma.sync.aligned.m16n8k16.row.col.f32.bf16.bf16.f32 "
                 "{%0,%1,%2,%3}, {%4,%5,%6,%7}, {%8,%9}, {%0,%1,%2,%3};"
                 : "+f"(c[0]), "+f"(c[1]), "+f"(c[2]), "+f"(c[3])
                 : "r"(a[0]), "r"(a[1]), "r"(a[2]), "r"(a[3]), "r"(b0), "r"(b1));
}

// ---------------------------------------------------------------------------
__global__ void init_w(const float* __restrict__ w) {
    int idx = blockIdx.x * 256 + threadIdx.x;       // 98304
    float v = w[idx];
    __nv_bfloat16 h = __float2bfloat16_rn(v);
    g_Wh[idx] = h;
    g_Wl[idx] = __float2bfloat16_rn(v - __bfloat162float(h));
    if (idx < DOUT) { g_sum[idx] = 0.f; g_sumsq[idx] = 0.f; }
}

// ---------------------------------------------------------------------------
__global__ void fps_kernel(const float* __restrict__ coor, float* __restrict__ out3) {
    __shared__ float sh[NSTK * 33];
    __shared__ float sd[NSTK];
    __shared__ int   si[NSTK];
    __shared__ int   sel[NHALF];
    int b = blockIdx.x, t = threadIdx.x;
    const float* src = coor + b * NSTK * 32;
#pragma unroll
    for (int r = 0; r < 32; r++) {
        int l = r * 64 + t;
        sh[(l >> 5) * 33 + (l & 31)] = src[l];
    }
    __syncthreads();
    float mind = 1e10f;
    int far = 0;
    const float* mine = sh + t * 33;
    for (int i = 0; i < NHALF; i++) {
        if (t == 0) { sel[i] = far; g_fps[b * NHALF + i] = far; }
        const float* cent = sh + far * 33;
        float d = 0.f;
#pragma unroll
        for (int c = 0; c < 32; c++) { float df = mine[c] - cent[c]; d = fmaf(df, df, d); }
        mind = fminf(mind, d);
        sd[t] = mind; si[t] = t;
        __syncthreads();
        for (int off = 32; off; off >>= 1) {
            if (t < off) {
                float d2 = sd[t + off]; int i2 = si[t + off];
                if (d2 > sd[t] || (d2 == sd[t] && i2 < si[t])) { sd[t] = d2; si[t] = i2; }
            }
            __syncthreads();
        }
        far = si[0];
        __syncthreads();
    }
#pragma unroll
    for (int r = 0; r < 16; r++) {
        int l = r * 64 + t;
        out3[b * 1024 + l] = sh[sel[l >> 5] * 33 + (l & 31)];
    }
}

// ---------------------------------------------------------------------------
__global__ void gather_sparse(const float* __restrict__ sp, float* __restrict__ outp) {
    int idx = blockIdx.x * 256 + threadIdx.x;
    int b = idx >> 13;
    int r = idx & 8191;
    int c = r >> 5, jj = r & 31;
    outp[idx] = sp[b * (SPEMB * NSTK) + c * NSTK + g_fps[b * NHALF + jj]];
}

// ---------------------------------------------------------------------------
// build_x: gather sampled strokes, im2col (3 taps, stride 2, left pad), hi/lo split
// ---------------------------------------------------------------------------
__global__ void __launch_bounds__(256) build_x(const float* __restrict__ dense) {
    __shared__ float xt[DIN * 64];
    int t = threadIdx.x;
    int bj = blockIdx.x;
    int b = bj >> 5;
    int s = g_fps[bj];
    const float4* src = reinterpret_cast<const float4*>(dense + (size_t)b * (DIN * 4096) + s * 64);
#pragma unroll
    for (int rep = 0; rep < 8; rep++) {
        int id = rep * 256 + t;
        int i = id >> 4, f4 = id & 15;
        reinterpret_cast<float4*>(xt)[i * 16 + f4] = src[i * 1024 + f4];
    }
    __syncthreads();
    size_t base = (size_t)bj * (QOUT * KTOT);
#pragma unroll 4
    for (int it = 0; it < 48; it++) {
        int e = it * 256 + t;
        int q = e / KTOT;
        int k = e - q * KTOT;
        int i = k / 3;
        int tap = k - i * 3;
        int pos = 2 * q - 1 + tap;
        float v = (pos >= 0) ? xt[i * 64 + pos] : 0.f;
        __nv_bfloat16 h = __float2bfloat16_rn(v);
        g_Xh[base + e] = h;
        g_Xl[base + e] = __float2bfloat16_rn(v - __bfloat162float(h));
    }
}

// ---------------------------------------------------------------------------
// HMMA GEMM: C[pos 65536, oc 256] = X[65536,384] * W[256,384]^T, 3 bf16 passes.
// CTA tile 128(pos) x 128(oc); warps 2(M) x 4(N) -> warp tile m64 x n32.
// 3-stage cp.async pipeline over 18 k64 chunks.
// ---------------------------------------------------------------------------
__global__ void __launch_bounds__(256) gemm_kernel() {
    extern __shared__ __align__(128) char smem[];
    uint32_t sb = smem_u32(smem);
    int t = threadIdx.x, wid = t >> 5, lane = t & 31;
    int ntile = blockIdx.x & 1, mt = blockIdx.x >> 1;
    int pbase = mt * 128, ocb = ntile * 128;
    int wm = wid & 1, wn = wid >> 1;            // warp tile origin (wm*64, wn*32)

    float acc[4][4][4];
#pragma unroll
    for (int i = 0; i < 4; i++)
#pragma unroll
        for (int j = 0; j < 4; j++)
#pragma unroll
            for (int k = 0; k < 4; k++) acc[i][j][k] = 0.f;

    const __nv_bfloat16* Aps[3] = { g_Xh, g_Xl, g_Xh };
    const __nv_bfloat16* Bps[3] = { g_Wh, g_Wh, g_Wl };

    auto load_chunk = [&](int c, int st) {
        int pass = c / 6;
        int k0 = (c - pass * 6) * 64;
        const __nv_bfloat16* A = Aps[pass];
        const __nv_bfloat16* B = Bps[pass];
        uint32_t ab = sb + st * STAGE_BYTES;
        uint32_t bb = ab + 16384;
#pragma unroll
        for (int rep = 0; rep < 4; rep++) {      // A: 128 rows x 8 x 16B
            int id = rep * 256 + t;
            int row = id >> 3, cc = id & 7;
            cp16(ab + SWZ(row * 128 + cc * 16),
                 A + (size_t)(pbase + row) * KTOT + k0 + cc * 8);
        }
#pragma unroll
        for (int rep = 0; rep < 4; rep++) {      // B: 128 rows x 8 x 16B
            int id = rep * 256 + t;
            int row = id >> 3, cc = id & 7;
            cp16(bb + SWZ(row * 128 + cc * 16),
                 B + (size_t)(ocb + row) * KTOT + k0 + cc * 8);
        }
    };

    auto compute_chunk = [&](int st) {
        uint32_t ab = sb + st * STAGE_BYTES;
        uint32_t bb = ab + 16384;
        int lr = lane & 15, lh = lane >> 4;      // ldmatrix row-in-16, 16B half
#pragma unroll
        for (int kk = 0; kk < 4; kk++) {
            uint32_t bA[4], bB[4];
            ldm4(bb + SWZ((wn * 32 + lr) * 128 + kk * 32 + lh * 16),
                 bA[0], bA[1], bA[2], bA[3]);
            ldm4(bb + SWZ((wn * 32 + 16 + lr) * 128 + kk * 32 + lh * 16),
                 bB[0], bB[1], bB[2], bB[3]);
#pragma unroll
            for (int mm = 0; mm < 4; mm++) {
                uint32_t a[4];
                ldm4(ab + SWZ((wm * 64 + mm * 16 + lr) * 128 + kk * 32 + lh * 16),
                     a[0], a[1], a[2], a[3]);
                mma16816(acc[mm][0], a, bA[0], bA[2]);
                mma16816(acc[mm][1], a, bA[1], bA[3]);
                mma16816(acc[mm][2], a, bB[0], bB[2]);
                mma16816(acc[mm][3], a, bB[1], bB[3]);
            }
        }
    };

    load_chunk(0, 0); CP_COMMIT();
    load_chunk(1, 1); CP_COMMIT();

    for (int c = 0; c < NCHUNK; c++) {
        __syncthreads();                          // everyone done with stage (c+2)%3
        if (c + 2 < NCHUNK) {
            load_chunk(c + 2, (c + 2) % 3);
            CP_COMMIT();
            asm volatile("cp.async.wait_group 2;" ::: "memory");
        } else if (c == NCHUNK - 2) {
            asm volatile("cp.async.wait_group 1;" ::: "memory");
        } else {
            asm volatile("cp.async.wait_group 0;" ::: "memory");
        }
        __syncthreads();                          // chunk c visible to all
        compute_chunk(c % 3);
    }

    // ---- BN partial stats straight from fragments ----
    __shared__ float ssum[128], ssq[128];
    if (t < 128) { ssum[t] = 0.f; ssq[t] = 0.f; }
    __syncthreads();
    {
        float s0 = 0.f, q0 = 0.f, s1 = 0.f, q1 = 0.f;
#pragma unroll
        for (int nn = 0; nn < 4; nn++) {
            s0 = 0.f; q0 = 0.f; s1 = 0.f; q1 = 0.f;
#pragma unroll
            for (int mm = 0; mm < 4; mm++) {
                float v0 = acc[mm][nn][0], v1 = acc[mm][nn][1];
                float v2 = acc[mm][nn][2], v3 = acc[mm][nn][3];
                s0 += v0 + v2; q0 += v0 * v0 + v2 * v2;
                s1 += v1 + v3; q1 += v1 * v1 + v3 * v3;
            }
            int n0 = wn * 32 + nn * 8 + (lane & 3) * 2;
            atomicAdd(&ssum[n0], s0);     atomicAdd(&ssq[n0], q0);
            atomicAdd(&ssum[n0 + 1], s1); atomicAdd(&ssq[n0 + 1], q1);
        }
    }

    // ---- epilogue: fragments -> smem [oc][pos] (stride 132) -> coalesced g_y ----
    __syncthreads();                              // pipeline smem reuse safe
    float* so = reinterpret_cast<float*>(smem);   // 128 x 132 floats = 67.5 KB
    {
        int r0 = wm * 64 + (lane >> 2);
#pragma unroll
        for (int mm = 0; mm < 4; mm++) {
            int rm = r0 + mm * 16;
#pragma unroll
            for (int nn = 0; nn < 4; nn++) {
                int n = wn * 32 + nn * 8 + (lane & 3) * 2;
                so[n * 132 + rm]           = acc[mm][nn][0];
                so[(n + 1) * 132 + rm]     = acc[mm][nn][1];
                so[n * 132 + rm + 8]       = acc[mm][nn][2];
                so[(n + 1) * 132 + rm + 8] = acc[mm][nn][3];
            }
        }
    }
    __syncthreads();

    if (t < 128) {
        atomicAdd(&g_sum[ocb + t], ssum[t]);
        atomicAdd(&g_sumsq[ocb + t], ssq[t]);
    }

    int b   = mt >> 3;
    int plb = (mt & 7) * 128;
#pragma unroll
    for (int it = 0; it < 16; it++) {
        int idx4 = it * 256 + t;                  // 4096 float4
        int n = idx4 >> 5, m4 = idx4 & 31;
        float4 v = *reinterpret_cast<const float4*>(so + n * 132 + m4 * 4);
        *reinterpret_cast<float4*>(g_y + (size_t)b * 262144 +
            (size_t)(ocb + n) * 1024 + plb + m4 * 4) = v;
    }
}

// ---------------------------------------------------------------------------
__global__ void bn_finalize(const float* __restrict__ gamma, const float* __restrict__ beta) {
    int t = threadIdx.x;
    const float inv_n = 1.f / 65536.f;
    float m = g_sum[t] * inv_n;
    float v = g_sumsq[t] * inv_n - m * m;
    float inv = rsqrtf(v + 1e-5f);
    float g = gamma[t] * inv;
    g_scale[t] = g;
    g_shift[t] = beta[t] - m * g;
}

__device__ __forceinline__ float gelu_t(float x) {
    float x3 = x * x * x;
    float u = 0.7978845608028654f * fmaf(0.044715f, x3, x);
    return 0.5f * x * (1.f + tanhf(u));
}

__global__ void bn_act_kernel(float* __restrict__ outp) {
    int idx4 = blockIdx.x * 256 + threadIdx.x;
    const float4* gy4 = reinterpret_cast<const float4*>(g_y);
    float4 v = gy4[idx4];
    int o = (idx4 >> 8) & 255;
    float sc = g_scale[o], sh = g_shift[o];
    v.x = gelu_t(fmaf(v.x, sc, sh));
    v.y = gelu_t(fmaf(v.y, sc, sh));
    v.z = gelu_t(fmaf(v.z, sc, sh));
    v.w = gelu_t(fmaf(v.w, sc, sh));
    reinterpret_cast<float4*>(outp)[idx4] = v;
}

// ---------------------------------------------------------------------------
extern "C" void kernel_launch(void* const* d_in, const int* in_sizes, int n_in,
                              void* d_out, int out_size) {
    const float* sparse = (const float*)d_in[0];
    const float* dense  = (const float*)d_in[1];
    const float* coor   = (const float*)d_in[2];
    const float* convw  = (const float*)d_in[3];
    const float* gamma  = (const float*)d_in[5];
    const float* beta   = (const float*)d_in[6];
    float* out = (float*)d_out;

    cudaFuncSetAttribute(gemm_kernel, cudaFuncAttributeMaxDynamicSharedMemorySize, DYN_SMEM);

    init_w<<<384, 256>>>(convw);
    fps_kernel<<<BSZ, 64>>>(coor, out + CO_OFF);
    gather_sparse<<<2048, 256>>>(sparse, out + SP_OFF);
    build_x<<<BSZ * NHALF, 256>>>(dense);
    gemm_kernel<<<1024, 256, DYN_SMEM>>>();
    bn_finalize<<<1, DOUT>>>(gamma, beta);
    bn_act_kernel<<<16384, 256>>>(out + DN_OFF);
}